// round 13
// baseline (speedup 1.0000x reference)
#include <cuda_runtime.h>
#include <math.h>

// Problem constants (B,S,D)=(2,2048,2048), H=16, KV=8, HD=128, N_REP=2
#define BB   2
#define SS   2048
#define DD   2048
#define HH   16
#define KVHN 8
#define HDIM 128

// Scratch (allocation-free rule: __device__ globals)
__device__ float g_q[(size_t)BB * HH * SS * HDIM];     // [B,H,S,HD]  (RoPE'd Q)
__device__ float g_k[(size_t)BB * KVHN * SS * HDIM];   // [B,KV,S,HD] (RoPE'd K)
__device__ float g_v[(size_t)BB * KVHN * SS * HDIM];   // [B,KV,S,HD]
__device__ float g_attn[(size_t)BB * SS * HH * HDIM];  // [B,S,H*HD]

// ---------------------------------------------------------------------------
// SGEMM: C = A[MxK] * B[KxN], all row-major. 128x128 block tile, BK=16,
// 256 threads, 8x8 per thread. MODE 0: plain row-major store.
// MODE 1: store into head-major scratch [B, nH, S, HD] (m=b*S+s, n=h*HD+d).
// ---------------------------------------------------------------------------
template <int MODE>
__global__ __launch_bounds__(256, 2) void sgemm_kernel(
    const float* __restrict__ A, const float* __restrict__ Bm,
    float* __restrict__ C, int M, int N, int K, int nH)
{
    __shared__ float As[16][128];   // [k][m]
    __shared__ float Bs[16][128];   // [k][n]

    const int tid = threadIdx.x;
    const int tr  = tid >> 4;   // 0..15  -> rows tr*8 .. tr*8+7
    const int tc  = tid & 15;   // 0..15  -> cols tc + 16*j
    const int m0  = blockIdx.y << 7;
    const int n0  = blockIdx.x << 7;

    float acc[8][8];
#pragma unroll
    for (int i = 0; i < 8; i++)
#pragma unroll
        for (int j = 0; j < 8; j++) acc[i][j] = 0.f;

    for (int k0 = 0; k0 < K; k0 += 16) {
        // Load A tile (128 rows x 16 cols) transposed into As[k][m]
#pragma unroll
        for (int q = 0; q < 2; q++) {
            const int idx = tid + (q << 8);       // 0..511 float4s
            const int r   = idx >> 2;             // row 0..127
            const int c   = (idx & 3) << 2;       // col 0,4,8,12
            const float4 v = *reinterpret_cast<const float4*>(
                A + (size_t)(m0 + r) * K + k0 + c);
            As[c + 0][r] = v.x;
            As[c + 1][r] = v.y;
            As[c + 2][r] = v.z;
            As[c + 3][r] = v.w;
        }
        // Load B tile (16 rows x 128 cols) straight into Bs[k][n]
#pragma unroll
        for (int q = 0; q < 2; q++) {
            const int idx = tid + (q << 8);
            const int r   = idx >> 5;             // k-row 0..15
            const int c   = (idx & 31) << 2;      // col 0..124 step 4
            *reinterpret_cast<float4*>(&Bs[r][c]) =
                *reinterpret_cast<const float4*>(
                    Bm + (size_t)(k0 + r) * N + n0 + c);
        }
        __syncthreads();

#pragma unroll
        for (int k = 0; k < 16; k++) {
            float a[8], b[8];
            const float4 a0 = *reinterpret_cast<const float4*>(&As[k][tr << 3]);
            const float4 a1 = *reinterpret_cast<const float4*>(&As[k][(tr << 3) + 4]);
            a[0] = a0.x; a[1] = a0.y; a[2] = a0.z; a[3] = a0.w;
            a[4] = a1.x; a[5] = a1.y; a[6] = a1.z; a[7] = a1.w;
#pragma unroll
            for (int j = 0; j < 8; j++) b[j] = Bs[k][tc + (j << 4)];
#pragma unroll
            for (int i = 0; i < 8; i++)
#pragma unroll
                for (int j = 0; j < 8; j++)
                    acc[i][j] = fmaf(a[i], b[j], acc[i][j]);
        }
        __syncthreads();
    }

    // Epilogue
#pragma unroll
    for (int i = 0; i < 8; i++) {
        const int m = m0 + (tr << 3) + i;
#pragma unroll
        for (int j = 0; j < 8; j++) {
            const int n = n0 + tc + (j << 4);
            if (MODE == 0) {
                C[(size_t)m * N + n] = acc[i][j];
            } else {
                const int bb = m >> 11;           // / SS (2048)
                const int s  = m & (SS - 1);
                const int h  = n >> 7;            // / HDIM
                const int d  = n & (HDIM - 1);
                C[(((size_t)bb * nH + h) * SS + s) * HDIM + d] = acc[i][j];
            }
        }
    }
}

// ---------------------------------------------------------------------------
// RoPE, in-place on [X, S, HD] buffer. Each thread owns a (d, d+64) pair.
// q' [d]    = x1*cos[s,d]    - x2*sin[s,d]        (rotate_half: -x2 for d<64)
// q' [d+64] = x2*cos[s,d+64] + x1*sin[s,d+64]
// ---------------------------------------------------------------------------
__global__ void rope_kernel(float* __restrict__ buf,
                            const float* __restrict__ cosb,
                            const float* __restrict__ sinb,
                            int total)
{
    const int idx = blockIdx.x * blockDim.x + threadIdx.x;
    if (idx >= total) return;
    const int d  = idx & 63;
    const int s  = (idx >> 6) & (SS - 1);
    const int xh = idx >> 17;                      // / (64*2048)
    float* row = buf + ((size_t)xh * SS + s) * HDIM;
    const float x1 = row[d];
    const float x2 = row[d + 64];
    const float c1 = cosb[s * HDIM + d];
    const float s1 = sinb[s * HDIM + d];
    const float c2 = cosb[s * HDIM + d + 64];
    const float s2 = sinb[s * HDIM + d + 64];
    row[d]      = fmaf(x1, c1, -x2 * s1);
    row[d + 64] = fmaf(x2, c2,  x1 * s2);
}

// ---------------------------------------------------------------------------
// Causal GQA flash attention, fp32, online softmax.
// Grid: (S/64, H, B). Block: 256 threads (ty=tid/16 rows, tx=tid%16 cols).
// 64x64 score tiles; rows owned = {ty+16r}, score cols = {tx+16c},
// O cols = {tx+16j}. Shared: Qs/Ks stride 129 (conflict-free [row][k] reads),
// Vs stride 128, P^T stride 65. Total 115456 B -> 2 CTAs/SM.
// ---------------------------------------------------------------------------
#define ATTN_SMEM_FLOATS (64 * 129 * 2 + 64 * 128 + 64 * 65)
#define ATTN_SMEM_BYTES  (ATTN_SMEM_FLOATS * 4)

__global__ __launch_bounds__(256, 2) void attn_kernel()
{
    extern __shared__ float smf[];
    float* Qs = smf;                  // [64][129]
    float* Ks = Qs + 64 * 129;        // [64][129]
    float* Vs = Ks + 64 * 129;        // [64][128]
    float* Pt = Vs + 64 * 128;        // [64 kcols][65]  (P transposed)

    const int qt  = (gridDim.x - 1) - blockIdx.x;   // heavy tiles first
    const int h   = blockIdx.y;
    const int b   = blockIdx.z;
    const int kvh = h >> 1;                          // N_REP = 2

    const int tid = threadIdx.x;
    const int ty  = tid >> 4;
    const int tx  = tid & 15;

    const float scale = 0.08838834764831845f;        // 1/sqrt(128)

    const float* qg  = g_q + (((size_t)b * HH  + h)   * SS + (size_t)qt * 64) * HDIM;
    const float* kg0 = g_k + (((size_t)b * KVHN + kvh) * SS) * HDIM;
    const float* vg0 = g_v + (((size_t)b * KVHN + kvh) * SS) * HDIM;

    // Load Q tile once, pre-scaled
#pragma unroll
    for (int it = 0; it < 32; it++) {
        const int idx = tid + (it << 8);   // 0..8191
        const int r   = idx >> 7;
        const int c   = idx & 127;
        Qs[r * 129 + c] = qg[(size_t)r * HDIM + c] * scale;
    }

    float m_i[4], l_i[4], acc[4][8];
#pragma unroll
    for (int r = 0; r < 4; r++) { m_i[r] = -3.0e38f; l_i[r] = 0.f; }
#pragma unroll
    for (int r = 0; r < 4; r++)
#pragma unroll
        for (int j = 0; j < 8; j++) acc[r][j] = 0.f;

    for (int kt = 0; kt <= qt; kt++) {
        __syncthreads();   // prev-iter Vs/Pt consumers done before overwrite

        const float* kg = kg0 + (size_t)(kt * 64) * HDIM;
        const float* vg = vg0 + (size_t)(kt * 64) * HDIM;
#pragma unroll
        for (int it = 0; it < 32; it++) {
            const int idx = tid + (it << 8);
            const int r   = idx >> 7;
            const int c   = idx & 127;
            Ks[r * 129 + c] = kg[(size_t)r * HDIM + c];
            Vs[r * 128 + c] = vg[(size_t)r * HDIM + c];
        }
        __syncthreads();

        // ---- Phase 1: S = Q K^T (64x64), rows ty+16r, cols tx+16c ----
        float sc[4][4];
#pragma unroll
        for (int r = 0; r < 4; r++)
#pragma unroll
            for (int c = 0; c < 4; c++) sc[r][c] = 0.f;

#pragma unroll 8
        for (int k = 0; k < 128; k++) {
            float qa[4], kb[4];
#pragma unroll
            for (int r = 0; r < 4; r++) qa[r] = Qs[(ty + (r << 4)) * 129 + k];
#pragma unroll
            for (int c = 0; c < 4; c++) kb[c] = Ks[(tx + (c << 4)) * 129 + k];
#pragma unroll
            for (int r = 0; r < 4; r++)
#pragma unroll
                for (int c = 0; c < 4; c++)
                    sc[r][c] = fmaf(qa[r], kb[c], sc[r][c]);
        }

        // Causal mask (only the diagonal tile can mask)
        if (kt == qt) {
#pragma unroll
            for (int r = 0; r < 4; r++)
#pragma unroll
                for (int c = 0; c < 4; c++)
                    if (tx + (c << 4) > ty + (r << 4)) sc[r][c] = -1.0e30f;
        }

        // ---- Online softmax: reduce across the 16 tx lanes per row ----
        float alpha[4];
#pragma unroll
        for (int r = 0; r < 4; r++) {
            float mr = fmaxf(fmaxf(sc[r][0], sc[r][1]), fmaxf(sc[r][2], sc[r][3]));
#pragma unroll
            for (int o = 1; o < 16; o <<= 1)
                mr = fmaxf(mr, __shfl_xor_sync(0xffffffffu, mr, o));
            const float mn = fmaxf(m_i[r], mr);
            alpha[r] = __expf(m_i[r] - mn);
            m_i[r]   = mn;
            float rs = 0.f;
#pragma unroll
            for (int c = 0; c < 4; c++) {
                const float p = __expf(sc[r][c] - mn);
                Pt[(tx + (c << 4)) * 65 + (ty + (r << 4))] = p;
                rs += p;
            }
#pragma unroll
            for (int o = 1; o < 16; o <<= 1)
                rs += __shfl_xor_sync(0xffffffffu, rs, o);
            l_i[r] = l_i[r] * alpha[r] + rs;
        }
        __syncthreads();   // P^T visible to all consumers

        // ---- Phase 2: O = O*alpha + P V, rows ty+16r, cols tx+16j ----
#pragma unroll
        for (int r = 0; r < 4; r++)
#pragma unroll
            for (int j = 0; j < 8; j++) acc[r][j] *= alpha[r];

#pragma unroll 4
        for (int k = 0; k < 64; k++) {
            float pa[4], vb[8];
#pragma unroll
            for (int r = 0; r < 4; r++) pa[r] = Pt[k * 65 + ty + (r << 4)];
#pragma unroll
            for (int j = 0; j < 8; j++) vb[j] = Vs[k * 128 + tx + (j << 4)];
#pragma unroll
            for (int r = 0; r < 4; r++)
#pragma unroll
                for (int j = 0; j < 8; j++)
                    acc[r][j] = fmaf(pa[r], vb[j], acc[r][j]);
        }
    }

    // Epilogue: normalize, write [B, S, H*HD] for the Wo GEMM
#pragma unroll
    for (int r = 0; r < 4; r++) {
        const float inv  = 1.f / l_i[r];
        const int   qrow = qt * 64 + ty + (r << 4);
        float* op = g_attn + ((size_t)b * SS + qrow) * (HH * HDIM) + h * HDIM;
#pragma unroll
        for (int j = 0; j < 8; j++)
            op[tx + (j << 4)] = acc[r][j] * inv;
    }
}

// ---------------------------------------------------------------------------
// Host launcher: all default-stream kernel launches, no sync, no alloc.
// Input order (metadata): x, cos, sin, Wq, Wk, Wv, Wo. Output: float32 [B,S,D].
// ---------------------------------------------------------------------------
extern "C" void kernel_launch(void* const* d_in, const int* in_sizes, int n_in,
                              void* d_out, int out_size)
{
    const float* x    = (const float*)d_in[0];
    const float* cosb = (const float*)d_in[1];
    const float* sinb = (const float*)d_in[2];
    const float* Wq   = (const float*)d_in[3];
    const float* Wk   = (const float*)d_in[4];
    const float* Wv   = (const float*)d_in[5];
    const float* Wo   = (const float*)d_in[6];
    float* out = (float*)d_out;

    float *qb, *kb, *vb, *ab;
    cudaGetSymbolAddress((void**)&qb, g_q);
    cudaGetSymbolAddress((void**)&kb, g_k);
    cudaGetSymbolAddress((void**)&vb, g_v);
    cudaGetSymbolAddress((void**)&ab, g_attn);

    cudaFuncSetAttribute(attn_kernel,
                         cudaFuncAttributeMaxDynamicSharedMemorySize,
                         ATTN_SMEM_BYTES);

    const int M = BB * SS;  // 4096

    // QKV projections (head-major scratch layouts)
    sgemm_kernel<1><<<dim3((HH * HDIM) / 128, M / 128), 256>>>(
        x, Wq, qb, M, HH * HDIM, DD, HH);
    sgemm_kernel<1><<<dim3((KVHN * HDIM) / 128, M / 128), 256>>>(
        x, Wk, kb, M, KVHN * HDIM, DD, KVHN);
    sgemm_kernel<1><<<dim3((KVHN * HDIM) / 128, M / 128), 256>>>(
        x, Wv, vb, M, KVHN * HDIM, DD, KVHN);

    // RoPE on Q and K (pair-safe in-place)
    rope_kernel<<<(BB * HH * SS * 64) / 256, 256>>>(qb, cosb, sinb,
                                                    BB * HH * SS * 64);
    rope_kernel<<<(BB * KVHN * SS * 64) / 256, 256>>>(kb, cosb, sinb,
                                                      BB * KVHN * SS * 64);

    // Causal GQA attention
    attn_kernel<<<dim3(SS / 64, HH, BB), 256, ATTN_SMEM_BYTES>>>();

    // Output projection straight into d_out
    sgemm_kernel<0><<<dim3(DD / 128, M / 128), 256>>>(
        ab, Wo, out, M, DD, DD, 0);
}

// round 14
// speedup vs baseline: 1.0038x; 1.0038x over previous
#include <cuda_runtime.h>
#include <math.h>

// Problem constants (B,S,D)=(2,2048,2048), H=16, KV=8, HD=128, N_REP=2
#define BB   2
#define SS   2048
#define DD   2048
#define HH   16
#define KVHN 8
#define HDIM 128

// Scratch (allocation-free rule: __device__ globals)
__device__ float g_q[(size_t)BB * HH * SS * HDIM];     // [B,H,S,HD]  (RoPE'd Q)
__device__ float g_k[(size_t)BB * KVHN * SS * HDIM];   // [B,KV,S,HD] (RoPE'd K)
__device__ float g_v[(size_t)BB * KVHN * SS * HDIM];   // [B,KV,S,HD]
__device__ float g_attn[(size_t)BB * SS * HH * HDIM];  // [B,S,H*HD]

// ---------------------------------------------------------------------------
// SGEMM: C = A[MxK] * B[KxN], all row-major. 128x128 block tile, BK=16,
// 256 threads, 8x8 per thread. MODE 0: plain row-major store.
// MODE 1: store into head-major scratch [B, nH, S, HD] (m=b*S+s, n=h*HD+d).
// ---------------------------------------------------------------------------
template <int MODE>
__global__ __launch_bounds__(256, 2) void sgemm_kernel(
    const float* __restrict__ A, const float* __restrict__ Bm,
    float* __restrict__ C, int M, int N, int K, int nH)
{
    __shared__ float As[16][128];   // [k][m]
    __shared__ float Bs[16][128];   // [k][n]

    const int tid = threadIdx.x;
    const int tr  = tid >> 4;   // 0..15  -> rows tr*8 .. tr*8+7
    const int tc  = tid & 15;   // 0..15  -> cols tc + 16*j
    const int m0  = blockIdx.y << 7;
    const int n0  = blockIdx.x << 7;

    float acc[8][8];
#pragma unroll
    for (int i = 0; i < 8; i++)
#pragma unroll
        for (int j = 0; j < 8; j++) acc[i][j] = 0.f;

    for (int k0 = 0; k0 < K; k0 += 16) {
        // Load A tile (128 rows x 16 cols) transposed into As[k][m]
#pragma unroll
        for (int q = 0; q < 2; q++) {
            const int idx = tid + (q << 8);       // 0..511 float4s
            const int r   = idx >> 2;             // row 0..127
            const int c   = (idx & 3) << 2;       // col 0,4,8,12
            const float4 v = *reinterpret_cast<const float4*>(
                A + (size_t)(m0 + r) * K + k0 + c);
            As[c + 0][r] = v.x;
            As[c + 1][r] = v.y;
            As[c + 2][r] = v.z;
            As[c + 3][r] = v.w;
        }
        // Load B tile (16 rows x 128 cols) straight into Bs[k][n]
#pragma unroll
        for (int q = 0; q < 2; q++) {
            const int idx = tid + (q << 8);
            const int r   = idx >> 5;             // k-row 0..15
            const int c   = (idx & 31) << 2;      // col 0..124 step 4
            *reinterpret_cast<float4*>(&Bs[r][c]) =
                *reinterpret_cast<const float4*>(
                    Bm + (size_t)(k0 + r) * N + n0 + c);
        }
        __syncthreads();

#pragma unroll
        for (int k = 0; k < 16; k++) {
            float a[8], b[8];
            const float4 a0 = *reinterpret_cast<const float4*>(&As[k][tr << 3]);
            const float4 a1 = *reinterpret_cast<const float4*>(&As[k][(tr << 3) + 4]);
            a[0] = a0.x; a[1] = a0.y; a[2] = a0.z; a[3] = a0.w;
            a[4] = a1.x; a[5] = a1.y; a[6] = a1.z; a[7] = a1.w;
#pragma unroll
            for (int j = 0; j < 8; j++) b[j] = Bs[k][tc + (j << 4)];
#pragma unroll
            for (int i = 0; i < 8; i++)
#pragma unroll
                for (int j = 0; j < 8; j++)
                    acc[i][j] = fmaf(a[i], b[j], acc[i][j]);
        }
        __syncthreads();
    }

    // Epilogue
#pragma unroll
    for (int i = 0; i < 8; i++) {
        const int m = m0 + (tr << 3) + i;
#pragma unroll
        for (int j = 0; j < 8; j++) {
            const int n = n0 + tc + (j << 4);
            if (MODE == 0) {
                C[(size_t)m * N + n] = acc[i][j];
            } else {
                const int bb = m >> 11;           // / SS (2048)
                const int s  = m & (SS - 1);
                const int h  = n >> 7;            // / HDIM
                const int d  = n & (HDIM - 1);
                C[(((size_t)bb * nH + h) * SS + s) * HDIM + d] = acc[i][j];
            }
        }
    }
}

// ---------------------------------------------------------------------------
// RoPE, in-place on [X, S, HD] buffer. Each thread owns a (d, d+64) pair.
// q' [d]    = x1*cos[s,d]    - x2*sin[s,d]        (rotate_half: -x2 for d<64)
// q' [d+64] = x2*cos[s,d+64] + x1*sin[s,d+64]
// ---------------------------------------------------------------------------
__global__ void rope_kernel(float* __restrict__ buf,
                            const float* __restrict__ cosb,
                            const float* __restrict__ sinb,
                            int total)
{
    const int idx = blockIdx.x * blockDim.x + threadIdx.x;
    if (idx >= total) return;
    const int d  = idx & 63;
    const int s  = (idx >> 6) & (SS - 1);
    const int xh = idx >> 17;                      // / (64*2048)
    float* row = buf + ((size_t)xh * SS + s) * HDIM;
    const float x1 = row[d];
    const float x2 = row[d + 64];
    const float c1 = cosb[s * HDIM + d];
    const float s1 = sinb[s * HDIM + d];
    const float c2 = cosb[s * HDIM + d + 64];
    const float s2 = sinb[s * HDIM + d + 64];
    row[d]      = fmaf(x1, c1, -x2 * s1);
    row[d + 64] = fmaf(x2, c2,  x1 * s2);
}

// ---------------------------------------------------------------------------
// Causal GQA flash attention, fp32, online softmax.
// Grid: (S/64, H, B). Block: 256 threads (ty=tid/16 rows, tx=tid%16 cols).
// 64x64 score tiles; rows owned = {ty+16r}, score cols = {tx+16c},
// O cols = {tx+16j}. Shared: Qs/Ks stride 129 (conflict-free [row][k] reads),
// Vs stride 128, P^T stride 65. Total 115456 B -> 2 CTAs/SM.
// ---------------------------------------------------------------------------
#define ATTN_SMEM_FLOATS (64 * 129 * 2 + 64 * 128 + 64 * 65)
#define ATTN_SMEM_BYTES  (ATTN_SMEM_FLOATS * 4)

__global__ __launch_bounds__(256, 2) void attn_kernel()
{
    extern __shared__ float smf[];
    float* Qs = smf;                  // [64][129]
    float* Ks = Qs + 64 * 129;        // [64][129]
    float* Vs = Ks + 64 * 129;        // [64][128]
    float* Pt = Vs + 64 * 128;        // [64 kcols][65]  (P transposed)

    const int qt  = (gridDim.x - 1) - blockIdx.x;   // heavy tiles first
    const int h   = blockIdx.y;
    const int b   = blockIdx.z;
    const int kvh = h >> 1;                          // N_REP = 2

    const int tid = threadIdx.x;
    const int ty  = tid >> 4;
    const int tx  = tid & 15;

    const float scale = 0.08838834764831845f;        // 1/sqrt(128)

    const float* qg  = g_q + (((size_t)b * HH  + h)   * SS + (size_t)qt * 64) * HDIM;
    const float* kg0 = g_k + (((size_t)b * KVHN + kvh) * SS) * HDIM;
    const float* vg0 = g_v + (((size_t)b * KVHN + kvh) * SS) * HDIM;

    // Load Q tile once, pre-scaled
#pragma unroll
    for (int it = 0; it < 32; it++) {
        const int idx = tid + (it << 8);   // 0..8191
        const int r   = idx >> 7;
        const int c   = idx & 127;
        Qs[r * 129 + c] = qg[(size_t)r * HDIM + c] * scale;
    }

    float m_i[4], l_i[4], acc[4][8];
#pragma unroll
    for (int r = 0; r < 4; r++) { m_i[r] = -3.0e38f; l_i[r] = 0.f; }
#pragma unroll
    for (int r = 0; r < 4; r++)
#pragma unroll
        for (int j = 0; j < 8; j++) acc[r][j] = 0.f;

    for (int kt = 0; kt <= qt; kt++) {
        __syncthreads();   // prev-iter Vs/Pt consumers done before overwrite

        const float* kg = kg0 + (size_t)(kt * 64) * HDIM;
        const float* vg = vg0 + (size_t)(kt * 64) * HDIM;
#pragma unroll
        for (int it = 0; it < 32; it++) {
            const int idx = tid + (it << 8);
            const int r   = idx >> 7;
            const int c   = idx & 127;
            Ks[r * 129 + c] = kg[(size_t)r * HDIM + c];
            Vs[r * 128 + c] = vg[(size_t)r * HDIM + c];
        }
        __syncthreads();

        // ---- Phase 1: S = Q K^T (64x64), rows ty+16r, cols tx+16c ----
        float sc[4][4];
#pragma unroll
        for (int r = 0; r < 4; r++)
#pragma unroll
            for (int c = 0; c < 4; c++) sc[r][c] = 0.f;

#pragma unroll 8
        for (int k = 0; k < 128; k++) {
            float qa[4], kb[4];
#pragma unroll
            for (int r = 0; r < 4; r++) qa[r] = Qs[(ty + (r << 4)) * 129 + k];
#pragma unroll
            for (int c = 0; c < 4; c++) kb[c] = Ks[(tx + (c << 4)) * 129 + k];
#pragma unroll
            for (int r = 0; r < 4; r++)
#pragma unroll
                for (int c = 0; c < 4; c++)
                    sc[r][c] = fmaf(qa[r], kb[c], sc[r][c]);
        }

        // Causal mask (only the diagonal tile can mask)
        if (kt == qt) {
#pragma unroll
            for (int r = 0; r < 4; r++)
#pragma unroll
                for (int c = 0; c < 4; c++)
                    if (tx + (c << 4) > ty + (r << 4)) sc[r][c] = -1.0e30f;
        }

        // ---- Online softmax: reduce across the 16 tx lanes per row ----
        float alpha[4];
#pragma unroll
        for (int r = 0; r < 4; r++) {
            float mr = fmaxf(fmaxf(sc[r][0], sc[r][1]), fmaxf(sc[r][2], sc[r][3]));
#pragma unroll
            for (int o = 1; o < 16; o <<= 1)
                mr = fmaxf(mr, __shfl_xor_sync(0xffffffffu, mr, o));
            const float mn = fmaxf(m_i[r], mr);
            alpha[r] = __expf(m_i[r] - mn);
            m_i[r]   = mn;
            float rs = 0.f;
#pragma unroll
            for (int c = 0; c < 4; c++) {
                const float p = __expf(sc[r][c] - mn);
                Pt[(tx + (c << 4)) * 65 + (ty + (r << 4))] = p;
                rs += p;
            }
#pragma unroll
            for (int o = 1; o < 16; o <<= 1)
                rs += __shfl_xor_sync(0xffffffffu, rs, o);
            l_i[r] = l_i[r] * alpha[r] + rs;
        }
        __syncthreads();   // P^T visible to all consumers

        // ---- Phase 2: O = O*alpha + P V, rows ty+16r, cols tx+16j ----
#pragma unroll
        for (int r = 0; r < 4; r++)
#pragma unroll
            for (int j = 0; j < 8; j++) acc[r][j] *= alpha[r];

#pragma unroll 4
        for (int k = 0; k < 64; k++) {
            float pa[4], vb[8];
#pragma unroll
            for (int r = 0; r < 4; r++) pa[r] = Pt[k * 65 + ty + (r << 4)];
#pragma unroll
            for (int j = 0; j < 8; j++) vb[j] = Vs[k * 128 + tx + (j << 4)];
#pragma unroll
            for (int r = 0; r < 4; r++)
#pragma unroll
                for (int j = 0; j < 8; j++)
                    acc[r][j] = fmaf(pa[r], vb[j], acc[r][j]);
        }
    }

    // Epilogue: normalize, write [B, S, H*HD] for the Wo GEMM
#pragma unroll
    for (int r = 0; r < 4; r++) {
        const float inv  = 1.f / l_i[r];
        const int   qrow = qt * 64 + ty + (r << 4);
        float* op = g_attn + ((size_t)b * SS + qrow) * (HH * HDIM) + h * HDIM;
#pragma unroll
        for (int j = 0; j < 8; j++)
            op[tx + (j << 4)] = acc[r][j] * inv;
    }
}

// ---------------------------------------------------------------------------
// Host launcher: all default-stream kernel launches, no sync, no alloc.
// Input order (metadata): x, cos, sin, Wq, Wk, Wv, Wo. Output: float32 [B,S,D].
// ---------------------------------------------------------------------------
extern "C" void kernel_launch(void* const* d_in, const int* in_sizes, int n_in,
                              void* d_out, int out_size)
{
    const float* x    = (const float*)d_in[0];
    const float* cosb = (const float*)d_in[1];
    const float* sinb = (const float*)d_in[2];
    const float* Wq   = (const float*)d_in[3];
    const float* Wk   = (const float*)d_in[4];
    const float* Wv   = (const float*)d_in[5];
    const float* Wo   = (const float*)d_in[6];
    float* out = (float*)d_out;

    float *qb, *kb, *vb, *ab;
    cudaGetSymbolAddress((void**)&qb, g_q);
    cudaGetSymbolAddress((void**)&kb, g_k);
    cudaGetSymbolAddress((void**)&vb, g_v);
    cudaGetSymbolAddress((void**)&ab, g_attn);

    cudaFuncSetAttribute(attn_kernel,
                         cudaFuncAttributeMaxDynamicSharedMemorySize,
                         ATTN_SMEM_BYTES);

    const int M = BB * SS;  // 4096

    // QKV projections (head-major scratch layouts)
    sgemm_kernel<1><<<dim3((HH * HDIM) / 128, M / 128), 256>>>(
        x, Wq, qb, M, HH * HDIM, DD, HH);
    sgemm_kernel<1><<<dim3((KVHN * HDIM) / 128, M / 128), 256>>>(
        x, Wk, kb, M, KVHN * HDIM, DD, KVHN);
    sgemm_kernel<1><<<dim3((KVHN * HDIM) / 128, M / 128), 256>>>(
        x, Wv, vb, M, KVHN * HDIM, DD, KVHN);

    // RoPE on Q and K (pair-safe in-place)
    rope_kernel<<<(BB * HH * SS * 64) / 256, 256>>>(qb, cosb, sinb,
                                                    BB * HH * SS * 64);
    rope_kernel<<<(BB * KVHN * SS * 64) / 256, 256>>>(kb, cosb, sinb,
                                                      BB * KVHN * SS * 64);

    // Causal GQA attention
    attn_kernel<<<dim3(SS / 64, HH, BB), 256, ATTN_SMEM_BYTES>>>();

    // Output projection straight into d_out
    sgemm_kernel<0><<<dim3(DD / 128, M / 128), 256>>>(
        ab, Wo, out, M, DD, DD, 0);
}